// round 17
// baseline (speedup 1.0000x reference)
#include <cuda_runtime.h>
#include <cuda_fp16.h>

// Shapes fixed by the problem: L=1024, D=640, K=32, M=64
#define LMAX 1024
#define MM   64
#define NT   512           // RBF table rows, d in [0, 64), h = 1/8  -> 64 KB fp16
#define TSCALE 8.0f

// fp16 scratch: nb (128 KB) + T (64 KB) -> L1-resident in edge kernel
__device__ __half g_nb16[LMAX * MM];
__device__ __half g_T16[NT * MM];

// ---------------------------------------------------------------------------
// Fused prep kernel (144 blocks):
//   [0,128)   : node projection, 8 rows each
//   [128,144) : RBF table, 32 t-rows each (w0 baked in)
// ---------------------------------------------------------------------------
__global__ void __launch_bounds__(256) prep_kernel(
    const float* __restrict__ S,
    const float* __restrict__ W_node,
    const float* __restrict__ b_edge,
    const float* __restrict__ rbf_mu,
    const float* __restrict__ rbf_sigma,
    const float* __restrict__ W_edge,
    int L, int D)
{
    __shared__ __align__(16) float sbuf[4672];
    const int tid = threadIdx.x;

    if (blockIdx.x < 128) {
        // ---------------- node projection: 8 rows ----------------
        float (*sS)[64] = reinterpret_cast<float (*)[64]>(sbuf);          // 8 x 64
        float (*sW)[65] = reinterpret_cast<float (*)[65]>(sbuf + 512);    // 64 x 65

        const int m  = tid & 63;
        const int jr = tid >> 6;
        const int j0 = blockIdx.x * 8;

        float a0 = 0.f, a1 = 0.f;
        float wreg[16], s0, s1;

        s0 = S[(size_t)(j0 + jr) * D + m];
        s1 = S[(size_t)(j0 + jr + 4) * D + m];
        #pragma unroll
        for (int r = 0; r < 16; r++)
            wreg[r] = W_node[(size_t)(r * 4 + jr) * MM + m];

        for (int d0 = 0; d0 < D; d0 += 64) {
            sS[jr][m]     = s0;
            sS[jr + 4][m] = s1;
            #pragma unroll
            for (int r = 0; r < 16; r++)
                sW[r * 4 + jr][m] = wreg[r];
            __syncthreads();
            int dn = d0 + 64;
            if (dn < D) {
                s0 = S[(size_t)(j0 + jr) * D + dn + m];
                s1 = S[(size_t)(j0 + jr + 4) * D + dn + m];
                #pragma unroll
                for (int r = 0; r < 16; r++)
                    wreg[r] = W_node[(size_t)(dn + r * 4 + jr) * MM + m];
            }
            #pragma unroll
            for (int d = 0; d < 64; d++) {
                float w = sW[d][m];
                a0 = fmaf(sS[jr][d], w, a0);
                a1 = fmaf(sS[jr + 4][d], w, a1);
            }
            __syncthreads();
        }
        float b = b_edge[m];
        g_nb16[(j0 + jr) * MM + m]     = __float2half_rn(a0 + b);
        g_nb16[(j0 + jr + 4) * MM + m] = __float2half_rn(a1 + b);
    } else {
        // ---------------- RBF table (+w0 baked): 32 rows ----------------
        float* se = sbuf;                       // 32 rows x 32 k
        const int t0   = (blockIdx.x - 128) * 32;
        const int m    = tid & 63;
        const int slot = tid >> 6;              // 0..3 -> rows slot*8..slot*8+7

        for (int v = tid; v < 32 * 32; v += 256) {
            int t = v >> 5, k = v & 31;
            float g  = (float)(t0 + t) * (1.0f / TSCALE);
            float mu = rbf_mu[k];
            float s  = rbf_sigma[k];
            float dd = g - mu;
            se[v] = __expf(-dd * dd / (2.0f * s * s));
        }
        float wreg[32];
        #pragma unroll
        for (int k = 0; k < 32; k++)
            wreg[k] = W_edge[(k + 2) * MM + m];
        const float w0 = W_edge[m];
        __syncthreads();

        float acc[8];
        #pragma unroll
        for (int r = 0; r < 8; r++) acc[r] = w0;
        #pragma unroll
        for (int k = 0; k < 32; k++) {
            float w = wreg[k];
            #pragma unroll
            for (int r = 0; r < 8; r++)
                acc[r] = fmaf(se[(slot * 8 + r) * 32 + k], w, acc[r]);
        }
        #pragma unroll
        for (int r = 0; r < 8; r++)
            g_T16[(size_t)(t0 + slot * 8 + r) * MM + m] = __float2half_rn(acc[r]);
    }
}

// ---------------------------------------------------------------------------
// Kernel 2: ONE row per block (grid L=1024). PDL secondary: compaction +
// geometry (input-only) run overlapped with prep; cudaGridDependencySynchronize
// gates the nb/T-consuming main loop. 6 CTAs/SM target.
// ---------------------------------------------------------------------------
__global__ void __launch_bounds__(256, 6) edge_kernel(
    const float* __restrict__ P,
    const float* __restrict__ xyz,
    const float* __restrict__ W_edge,
    const float* __restrict__ w_out,
    float* __restrict__ out,
    int L)
{
    __shared__ int    sJI[LMAX];                 // j | (it<<16)
    __shared__ __half sPh[LMAX];
    __shared__ float  sDx[LMAX], sDy[LMAX], sDz[LMAX];
    __shared__ int    wsum[8];
    __shared__ float  sred[8][3];

    const int tid  = threadIdx.x;
    const int lane = tid & 31;
    const int wrp  = tid >> 5;
    const int sub  = lane & 7;    // m-slice within edge group
    const int es   = lane >> 3;   // edge slot (0..3)
    const int i    = blockIdx.x;

    // per-lane weight slices as half2 (inputs; safe pre-sync)
    const int mb = sub * 8;
    __half2 w1h[4], woh[4];
    {
        float4 c = *(const float4*)(W_edge + MM + mb);
        float4 d = *(const float4*)(W_edge + MM + mb + 4);
        float4 e = *(const float4*)(w_out + mb);
        float4 f = *(const float4*)(w_out + mb + 4);
        w1h[0] = __floats2half2_rn(c.x, c.y);
        w1h[1] = __floats2half2_rn(c.z, c.w);
        w1h[2] = __floats2half2_rn(d.x, d.y);
        w1h[3] = __floats2half2_rn(d.z, d.w);
        woh[0] = __floats2half2_rn(e.x, e.y);
        woh[1] = __floats2half2_rn(e.z, e.w);
        woh[2] = __floats2half2_rn(f.x, f.y);
        woh[3] = __floats2half2_rn(f.z, f.w);
    }
    const __half2 hz = __float2half2_rn(0.f);

    const float xi = xyz[i * 3 + 0];
    const float yi = xyz[i * 3 + 1];
    const float zi = xyz[i * 3 + 2];

    // ---- two-pass compaction: CONTACT edges only (pre-sync, inputs only) ----
    const float4 p4 = reinterpret_cast<const float4*>(P + (size_t)i * L)[tid];
    float pv[4] = {p4.x, p4.y, p4.z, p4.w};
    const int jb = tid * 4;

    int c = 0;
    #pragma unroll
    for (int r = 0; r < 4; r++)
        c += ((pv[r] > 0.2f) && (jb + r > i + 2)) ? 1 : 0;

    int inc = c;
    #pragma unroll
    for (int off = 1; off < 32; off <<= 1) {
        int v = __shfl_up_sync(0xffffffffu, inc, off);
        if (lane >= off) inc += v;
    }
    if (lane == 31) wsum[wrp] = inc;
    __syncthreads();
    int offset = inc - c;
    int total  = 0;
    #pragma unroll
    for (int q = 0; q < 8; q++) {
        int wv = wsum[q];
        if (q < wrp) offset += wv;
        total += wv;
    }
    // pass 2: recompute predicate, store directly
    #pragma unroll
    for (int r = 0; r < 4; r++) {
        if ((pv[r] > 0.2f) && (jb + r > i + 2)) {
            sJI[offset] = jb + r;
            sPh[offset] = __float2half_rn(pv[r]);
            offset++;
        }
    }
    __syncthreads();

    const int padded = (total + 63) & ~63;

    // ---- per-edge geometry + packed (j, table index) (pre-sync) ----
    for (int e = tid; e < padded; e += 256) {
        if (e < total) {
            int j = sJI[e];
            float dx = xyz[3 * j + 0] - xi;
            float dy = xyz[3 * j + 1] - yi;
            float dz = xyz[3 * j + 2] - zi;
            float d  = sqrtf(fmaf(dx, dx, fmaf(dy, dy, fmaf(dz, dz, 1e-12f))));
            int it = (int)(d * TSCALE + 0.5f);
            it = (it > NT - 1) ? (NT - 1) : it;
            sJI[e] = j | (it << 16);
            sDx[e] = dx; sDy[e] = dy; sDz[e] = dz;
        } else {
            sJI[e] = 0; sPh[e] = __float2half_rn(0.f);
            sDx[e] = 0.f; sDy[e] = 0.f; sDz[e] = 0.f;
        }
    }
    __syncthreads();

    // ---- PDL gate: wait for prep_kernel's nb/T writes ----
    cudaGridDependencySynchronize();

    // ---- main loop: 8 edges per warp-iteration, full half2 math ----
    float ax = 0.f, ay = 0.f, az = 0.f;
    for (int eb = wrp * 8; eb < padded; eb += 64) {
        const int e1 = eb + es;
        const int e2 = eb + 4 + es;
        const int ji1 = sJI[e1], ji2 = sJI[e2];
        const __half2 p1h = __half2half2(sPh[e1]);
        const __half2 p2h = __half2half2(sPh[e2]);
        const int j1 = ji1 & 0xFFFF, it1 = ji1 >> 16;
        const int j2 = ji2 & 0xFFFF, it2 = ji2 >> 16;

        uint4 nb1 = *reinterpret_cast<const uint4*>(g_nb16 + j1 * MM + mb);
        uint4 tv1 = *reinterpret_cast<const uint4*>(g_T16 + (size_t)it1 * MM + mb);
        uint4 nb2 = *reinterpret_cast<const uint4*>(g_nb16 + j2 * MM + mb);
        uint4 tv2 = *reinterpret_cast<const uint4*>(g_T16 + (size_t)it2 * MM + mb);

        const __half2* nh1 = reinterpret_cast<const __half2*>(&nb1);
        const __half2* th1 = reinterpret_cast<const __half2*>(&tv1);
        const __half2* nh2 = reinterpret_cast<const __half2*>(&nb2);
        const __half2* th2 = reinterpret_cast<const __half2*>(&tv2);

        __half2 g1h = hz, g2h = hz;
        #pragma unroll
        for (int q = 0; q < 4; q++) {
            __half2 m1 = __hfma2(p1h, w1h[q], __hadd2(nh1[q], th1[q]));
            __half2 m2 = __hfma2(p2h, w1h[q], __hadd2(nh2[q], th2[q]));
            m1 = __hmax2(m1, hz);
            m2 = __hmax2(m2, hz);
            g1h = __hfma2(m1, woh[q], g1h);
            g2h = __hfma2(m2, woh[q], g2h);
        }
        float2 gf1 = __half22float2(g1h);
        float2 gf2 = __half22float2(g2h);
        float g1 = gf1.x + gf1.y;
        float g2 = gf2.x + gf2.y;

        g1 += __shfl_xor_sync(0xffffffffu, g1, 1);
        g2 += __shfl_xor_sync(0xffffffffu, g2, 1);
        g1 += __shfl_xor_sync(0xffffffffu, g1, 2);
        g2 += __shfl_xor_sync(0xffffffffu, g2, 2);
        g1 += __shfl_xor_sync(0xffffffffu, g1, 4);
        g2 += __shfl_xor_sync(0xffffffffu, g2, 4);

        if (sub == 0) {
            if (e1 < total) {
                float gate = __fdividef(1.f, 1.f + __expf(-g1));
                ax = fmaf(gate, sDx[e1], ax);
                ay = fmaf(gate, sDy[e1], ay);
                az = fmaf(gate, sDz[e1], az);
            }
            if (e2 < total) {
                float gate = __fdividef(1.f, 1.f + __expf(-g2));
                ax = fmaf(gate, sDx[e2], ax);
                ay = fmaf(gate, sDy[e2], ay);
                az = fmaf(gate, sDz[e2], az);
            }
        }
    }

    // ---- backbone edge (j = i+1): warp 0, float math, 2 m per lane ----
    if (wrp == 0 && i + 1 < L) {
        const int j = i + 1;
        const float dx = xyz[3 * j + 0] - xi;
        const float dy = xyz[3 * j + 1] - yi;
        const float dz = xyz[3 * j + 2] - zi;
        const float d  = sqrtf(fmaf(dx, dx, fmaf(dy, dy, fmaf(dz, dz, 1e-12f))));
        int it = (int)(d * TSCALE + 0.5f);
        it = (it > NT - 1) ? (NT - 1) : it;

        const int m2 = lane * 2;
        __half2 nb = *reinterpret_cast<const __half2*>(g_nb16 + j * MM + m2);
        __half2 tv = *reinterpret_cast<const __half2*>(g_T16 + (size_t)it * MM + m2);
        float2 f  = __half22float2(__hadd2(nb, tv));
        float2 w0 = *reinterpret_cast<const float2*>(W_edge + m2);
        float2 w1 = *reinterpret_cast<const float2*>(W_edge + MM + m2);
        float2 wo = *reinterpret_cast<const float2*>(w_out + m2);
        // msg = nb + T + w1 = nb + T' - w0 + w1  (et=0, pij=1)
        float a0 = f.x - w0.x + w1.x;
        float a1 = f.y - w0.y + w1.y;
        float gb = fmaf(fmaxf(a0, 0.f), wo.x, fmaxf(a1, 0.f) * wo.y);
        #pragma unroll
        for (int off = 16; off; off >>= 1)
            gb += __shfl_down_sync(0xffffffffu, gb, off);
        if (lane == 0) {
            float gate = __fdividef(1.f, 1.f + __expf(-gb));
            ax = fmaf(gate, dx, ax);
            ay = fmaf(gate, dy, ay);
            az = fmaf(gate, dz, az);
        }
    }

    // ---- deterministic block reduction ----
    #pragma unroll
    for (int off = 16; off; off >>= 1) {
        ax += __shfl_down_sync(0xffffffffu, ax, off);
        ay += __shfl_down_sync(0xffffffffu, ay, off);
        az += __shfl_down_sync(0xffffffffu, az, off);
    }
    if (lane == 0) { sred[wrp][0] = ax; sred[wrp][1] = ay; sred[wrp][2] = az; }
    __syncthreads();
    if (tid == 0) {
        float tx = 0.f, ty = 0.f, tz = 0.f;
        #pragma unroll
        for (int q = 0; q < 8; q++) { tx += sred[q][0]; ty += sred[q][1]; tz += sred[q][2]; }
        out[i * 3 + 0] = xi + tx;
        out[i * 3 + 1] = yi + ty;
        out[i * 3 + 2] = zi + tz;
    }
}

// ---------------------------------------------------------------------------
extern "C" void kernel_launch(void* const* d_in, const int* in_sizes, int n_in,
                              void* d_out, int out_size)
{
    const float* S         = (const float*)d_in[0];
    const float* P         = (const float*)d_in[1];
    const float* xyz       = (const float*)d_in[2];
    const float* rbf_mu    = (const float*)d_in[3];
    const float* rbf_sigma = (const float*)d_in[4];
    const float* W_edge    = (const float*)d_in[5];
    const float* b_edge    = (const float*)d_in[6];
    const float* W_node    = (const float*)d_in[7];
    const float* w_out     = (const float*)d_in[8];
    float* out = (float*)d_out;

    int L = in_sizes[2] / 3;          // 1024
    int D = in_sizes[0] / L;          // 640

    prep_kernel<<<128 + NT / 32, 256>>>(S, W_node, b_edge,
                                        rbf_mu, rbf_sigma, W_edge, L, D);

    // PDL launch: edge kernel starts while prep runs; its input-only phases
    // overlap prep, cudaGridDependencySynchronize gates the nb/T consumers.
    cudaLaunchConfig_t cfg = {};
    cfg.gridDim  = dim3((unsigned)L, 1, 1);
    cfg.blockDim = dim3(256, 1, 1);
    cfg.dynamicSmemBytes = 0;
    cfg.stream = 0;
    cudaLaunchAttribute attrs[1];
    attrs[0].id = cudaLaunchAttributeProgrammaticStreamSerialization;
    attrs[0].val.programmaticStreamSerializationAllowed = 1;
    cfg.attrs = attrs;
    cfg.numAttrs = 1;
    cudaLaunchKernelEx(&cfg, edge_kernel, P, xyz, W_edge, w_out, out, L);
}